// round 1
// baseline (speedup 1.0000x reference)
#include <cuda_runtime.h>
#include <cstdint>

#define SEQ    2048
#define BATCH  4
#define NHEAD  16
#define DK     64
#define DMODEL 1024
#define MROWS  (BATCH*SEQ)

// Scratch (allocation-free rule: device globals). 4 x 32MB.
__device__ float g_q[BATCH*NHEAD*SEQ*DK];
__device__ float g_k[BATCH*NHEAD*SEQ*DK];
__device__ float g_v[BATCH*NHEAD*SEQ*DK];
__device__ float g_ctx[(size_t)MROWS*DMODEL];

// ---------------- helpers ----------------
__device__ __forceinline__ uint32_t f2tf(float x){
    uint32_t r; asm("cvt.rna.tf32.f32 %0, %1;" : "=r"(r) : "f"(x)); return r;
}
__device__ __forceinline__ float tff(float x){ return __uint_as_float(f2tf(x)); }
__device__ __forceinline__ uint32_t saddr(const void* p){
    return (uint32_t)__cvta_generic_to_shared(p);
}
__device__ __forceinline__ void cp16(uint32_t s, const void* g){
    asm volatile("cp.async.cg.shared.global [%0], [%1], 16;\n" :: "r"(s), "l"(g));
}
__device__ __forceinline__ void cpcommit(){ asm volatile("cp.async.commit_group;\n"); }
template<int N> __device__ __forceinline__ void cpwait(){
    asm volatile("cp.async.wait_group %0;\n" :: "n"(N));
}
// m16n8k8 tf32 MMA, row.col, fp32 accumulate (D==C in-place)
__device__ __forceinline__ void mma8(float c[4],
        uint32_t a0,uint32_t a1,uint32_t a2,uint32_t a3,
        uint32_t b0,uint32_t b1){
    asm volatile(
      "mma.sync.aligned.m16n8k8.row.col.f32.tf32.tf32.f32 "
      "{%0,%1,%2,%3},{%4,%5,%6,%7},{%8,%9},{%0,%1,%2,%3};\n"
      : "+f"(c[0]), "+f"(c[1]), "+f"(c[2]), "+f"(c[3])
      : "r"(a0), "r"(a1), "r"(a2), "r"(a3), "r"(b0), "r"(b1));
}

// ---------------- GEMM: C[M,N] = X[M,K] @ W[N,K]^T + bias ----------------
// M=8192, N=K=1024. Block tile 128x128x32, 256 threads (8 warps = 4Mx2N),
// warp tile 32x64 (2 m16-tiles x 8 n8-tiles). Double-buffered cp.async.
// mode 0: dst[m*1024+n] = val (fp32)           (output projection)
// mode 1: head-split store to [B,H,S,64], scaled, pre-rounded to tf32 (QKV)
#define GEMM_SMEM_BYTES (4*128*36*4)

__global__ void __launch_bounds__(256,1) gemm_tf32(
    const float* __restrict__ A, const float* __restrict__ W,
    const float* __restrict__ bias, float* __restrict__ dst,
    int mode, float scale)
{
    extern __shared__ float sm[];
    float* sA = sm;                 // [2][128][36]
    float* sB = sm + 2*128*36;      // [2][128][36]
    const int tid = threadIdx.x;
    const int m0 = blockIdx.y << 7, n0 = blockIdx.x << 7;

    auto load_tile = [&](int buf, int kt){
        const float* Ag = A + (size_t)m0*DMODEL + kt*32;
        const float* Wg = W + (size_t)n0*DMODEL + kt*32;
        float* a = sA + buf*(128*36);
        float* b = sB + buf*(128*36);
#pragma unroll
        for (int i = 0; i < 4; ++i){
            int v = i*256 + tid;
            int r = v >> 3, c = (v & 7) << 2;
            cp16(saddr(a + r*36 + c), Ag + (size_t)r*DMODEL + c);
            cp16(saddr(b + r*36 + c), Wg + (size_t)r*DMODEL + c);
        }
        cpcommit();
    };

    float acc[2][8][4];
#pragma unroll
    for (int i=0;i<2;i++)
#pragma unroll
        for (int j=0;j<8;j++)
#pragma unroll
            for (int e=0;e<4;e++) acc[i][j][e] = 0.f;

    load_tile(0, 0);

    const int warp = tid >> 5, lane = tid & 31;
    const int wm = warp >> 1, wn = warp & 1;
    const int g = lane >> 2, tig = lane & 3;

    for (int kt = 0; kt < 32; ++kt){
        if (kt < 31){ load_tile((kt+1)&1, kt+1); cpwait<1>(); }
        else        { cpwait<0>(); }
        __syncthreads();
        const float* a = sA + (kt&1)*(128*36);
        const float* b = sB + (kt&1)*(128*36);
#pragma unroll
        for (int ks = 0; ks < 4; ++ks){
            uint32_t af[2][4];
#pragma unroll
            for (int mt = 0; mt < 2; ++mt){
                int r = wm*32 + mt*16 + g;
                int c = ks*8 + tig;
                af[mt][0] = f2tf(a[r*36 + c]);
                af[mt][1] = f2tf(a[(r+8)*36 + c]);
                af[mt][2] = f2tf(a[r*36 + c + 4]);
                af[mt][3] = f2tf(a[(r+8)*36 + c + 4]);
            }
#pragma unroll
            for (int nt = 0; nt < 8; ++nt){
                int n = wn*64 + nt*8 + g;
                int c = ks*8 + tig;
                uint32_t b0 = f2tf(b[n*36 + c]);
                uint32_t b1 = f2tf(b[n*36 + c + 4]);
                mma8(acc[0][nt], af[0][0],af[0][1],af[0][2],af[0][3], b0,b1);
                mma8(acc[1][nt], af[1][0],af[1][1],af[1][2],af[1][3], b0,b1);
            }
        }
        __syncthreads();
    }

    // epilogue
#pragma unroll
    for (int mt = 0; mt < 2; ++mt){
#pragma unroll
        for (int nt = 0; nt < 8; ++nt){
            int row = m0 + wm*32 + mt*16 + g;
            int col = n0 + wn*64 + nt*8 + 2*tig;
#pragma unroll
            for (int e = 0; e < 4; ++e){
                int r  = row + (e >> 1)*8;
                int cc = col + (e & 1);
                float val = (acc[mt][nt][e] + bias[cc]) * scale;
                if (mode == 0){
                    dst[(size_t)r*DMODEL + cc] = val;
                } else {
                    int bb = r >> 11, s = r & 2047, h = cc >> 6, d = cc & 63;
                    dst[(((size_t)(bb*NHEAD + h))*SEQ + s)*DK + d] = tff(val);
                }
            }
        }
    }
}

// ---------------- Flash attention (per (b,h), 128-row Q tiles) ----------------
// 256 threads = 8 warps; warp w owns Q rows [w*16, w*16+16) of the tile, so
// softmax rows never cross warps. K/V chunks of 128 keys, online softmax,
// P staged via per-warp smem slab for the PV MMA.
#define ATTN_SMEM_BYTES ((2*128*68 + 8*16*132)*4)

__global__ void __launch_bounds__(256,1) attn_kernel()
{
    extern __shared__ float sm[];
    float* sK = sm;                   // [128][68]
    float* sV = sm + 128*68;          // [128][68]
    float* sP = sm + 2*128*68;        // [8][16][132]; also Q staging [128][68]

    const int tid  = threadIdx.x;
    const int warp = tid >> 5, lane = tid & 31;
    const int g = lane >> 2, tig = lane & 3;
    const int qt = blockIdx.x, bh = blockIdx.y;

    const float* qg  = g_q + ((size_t)bh*SEQ + qt*128)*DK;  // pre-scaled by 1/8
    const float* kg0 = g_k + (size_t)bh*SEQ*DK;
    const float* vg0 = g_v + (size_t)bh*SEQ*DK;

    // stage Q tile (reuses sP region), then lift A-fragments to registers
#pragma unroll
    for (int i = 0; i < 8; ++i){
        int v = i*256 + tid;
        int r = v >> 4, c = (v & 15) << 2;
        cp16(saddr(sP + r*68 + c), qg + (size_t)r*DK + c);
    }
    cpcommit(); cpwait<0>(); __syncthreads();

    uint32_t qa[8][4];
#pragma unroll
    for (int kk = 0; kk < 8; ++kk){
        int r = warp*16 + g;
        int c = kk*8 + tig;
        qa[kk][0] = __float_as_uint(sP[r*68 + c]);
        qa[kk][1] = __float_as_uint(sP[(r+8)*68 + c]);
        qa[kk][2] = __float_as_uint(sP[r*68 + c + 4]);
        qa[kk][3] = __float_as_uint(sP[(r+8)*68 + c + 4]);
    }
    __syncthreads();

    float o[8][4];
#pragma unroll
    for (int j=0;j<8;j++)
#pragma unroll
        for (int e=0;e<4;e++) o[j][e] = 0.f;
    float rm0 = -1e30f, rm1 = -1e30f, rl0 = 0.f, rl1 = 0.f;

    float* myP = sP + warp*(16*132);

    for (int kt = 0; kt < 16; ++kt){
        __syncthreads();  // all warps done reading sK/sV of previous chunk
        const float* kg = kg0 + (size_t)kt*128*DK;
        const float* vg = vg0 + (size_t)kt*128*DK;
#pragma unroll
        for (int i = 0; i < 8; ++i){
            int v = i*256 + tid;
            int r = v >> 4, c = (v & 15) << 2;
            cp16(saddr(sK + r*68 + c), kg + (size_t)r*DK + c);
            cp16(saddr(sV + r*68 + c), vg + (size_t)r*DK + c);
        }
        cpcommit(); cpwait<0>(); __syncthreads();

        // S[16 x 128] = q @ K^T (q pre-scaled)
        float s[16][4];
#pragma unroll
        for (int j=0;j<16;j++)
#pragma unroll
            for (int e=0;e<4;e++) s[j][e] = 0.f;
#pragma unroll
        for (int kk = 0; kk < 8; ++kk){
#pragma unroll
            for (int nt = 0; nt < 16; ++nt){
                int n = nt*8 + g;
                int c = kk*8 + tig;
                uint32_t b0 = __float_as_uint(sK[n*68 + c]);
                uint32_t b1 = __float_as_uint(sK[n*68 + c + 4]);
                mma8(s[nt], qa[kk][0],qa[kk][1],qa[kk][2],qa[kk][3], b0,b1);
            }
        }

        // online softmax (rows g and g+8, private to this warp)
        float m0c = -1e30f, m1c = -1e30f;
#pragma unroll
        for (int nt = 0; nt < 16; ++nt){
            m0c = fmaxf(m0c, fmaxf(s[nt][0], s[nt][1]));
            m1c = fmaxf(m1c, fmaxf(s[nt][2], s[nt][3]));
        }
        m0c = fmaxf(m0c, __shfl_xor_sync(0xffffffffu, m0c, 1));
        m0c = fmaxf(m0c, __shfl_xor_sync(0xffffffffu, m0c, 2));
        m1c = fmaxf(m1c, __shfl_xor_sync(0xffffffffu, m1c, 1));
        m1c = fmaxf(m1c, __shfl_xor_sync(0xffffffffu, m1c, 2));
        float nm0 = fmaxf(rm0, m0c), nm1 = fmaxf(rm1, m1c);
        float cor0 = __expf(rm0 - nm0), cor1 = __expf(rm1 - nm1);
        rm0 = nm0; rm1 = nm1;

        float l0 = 0.f, l1 = 0.f;
#pragma unroll
        for (int nt = 0; nt < 16; ++nt){
            float p0 = __expf(s[nt][0] - nm0);
            float p1 = __expf(s[nt][1] - nm0);
            float p2 = __expf(s[nt][2] - nm1);
            float p3 = __expf(s[nt][3] - nm1);
            l0 += p0 + p1; l1 += p2 + p3;
            *(float2*)(myP + g*132     + nt*8 + 2*tig) = make_float2(tff(p0), tff(p1));
            *(float2*)(myP + (g+8)*132 + nt*8 + 2*tig) = make_float2(tff(p2), tff(p3));
        }
        l0 += __shfl_xor_sync(0xffffffffu, l0, 1);
        l0 += __shfl_xor_sync(0xffffffffu, l0, 2);
        l1 += __shfl_xor_sync(0xffffffffu, l1, 1);
        l1 += __shfl_xor_sync(0xffffffffu, l1, 2);
        rl0 = rl0*cor0 + l0;
        rl1 = rl1*cor1 + l1;

#pragma unroll
        for (int j = 0; j < 8; ++j){
            o[j][0]*=cor0; o[j][1]*=cor0; o[j][2]*=cor1; o[j][3]*=cor1;
        }
        __syncwarp();  // P writes visible to all lanes of this warp

        // O += P @ V
#pragma unroll
        for (int kk = 0; kk < 16; ++kk){
            int c = kk*8 + tig;
            uint32_t a0 = __float_as_uint(myP[g*132 + c]);
            uint32_t a1 = __float_as_uint(myP[(g+8)*132 + c]);
            uint32_t a2 = __float_as_uint(myP[g*132 + c + 4]);
            uint32_t a3 = __float_as_uint(myP[(g+8)*132 + c + 4]);
#pragma unroll
            for (int nt = 0; nt < 8; ++nt){
                uint32_t b0 = __float_as_uint(sV[c*68 + nt*8 + g]);
                uint32_t b1 = __float_as_uint(sV[(c+4)*68 + nt*8 + g]);
                mma8(o[nt], a0,a1,a2,a3, b0,b1);
            }
        }
        __syncwarp();  // lanes done reading P before next chunk overwrites it
    }

    // normalize + write context in [B,S,D] layout (pre-rounded to tf32)
    float il0 = 1.f/rl0, il1 = 1.f/rl1;
    int b = bh >> 4, h = bh & 15;
    int r0 = b*SEQ + qt*128 + warp*16 + g;
#pragma unroll
    for (int nt = 0; nt < 8; ++nt){
        int col = h*64 + nt*8 + 2*tig;
        *(float2*)(g_ctx + (size_t)r0*DMODEL + col) =
            make_float2(tff(o[nt][0]*il0), tff(o[nt][1]*il0));
        *(float2*)(g_ctx + (size_t)(r0+8)*DMODEL + col) =
            make_float2(tff(o[nt][2]*il1), tff(o[nt][3]*il1));
    }
}

// ---------------- launch ----------------
extern "C" void kernel_launch(void* const* d_in, const int* in_sizes, int n_in,
                              void* d_out, int out_size)
{
    const float* Xq = (const float*)d_in[0];
    const float* Xk = (const float*)d_in[1];
    const float* Xv = (const float*)d_in[2];
    const float* Wq = (const float*)d_in[3]; const float* bq = (const float*)d_in[4];
    const float* Wk = (const float*)d_in[5]; const float* bk = (const float*)d_in[6];
    const float* Wv = (const float*)d_in[7]; const float* bv = (const float*)d_in[8];
    const float* Wo = (const float*)d_in[9]; const float* bo = (const float*)d_in[10];
    float* out = (float*)d_out;

    void *gq, *gk, *gv, *gctx;
    cudaGetSymbolAddress(&gq,  g_q);
    cudaGetSymbolAddress(&gk,  g_k);
    cudaGetSymbolAddress(&gv,  g_v);
    cudaGetSymbolAddress(&gctx, g_ctx);

    cudaFuncSetAttribute(gemm_tf32,  cudaFuncAttributeMaxDynamicSharedMemorySize, GEMM_SMEM_BYTES);
    cudaFuncSetAttribute(attn_kernel, cudaFuncAttributeMaxDynamicSharedMemorySize, ATTN_SMEM_BYTES);

    dim3 gg(DMODEL/128, MROWS/128);   // (8, 64)
    // Q projection: fold the 1/sqrt(d_k)=1/8 score scale into Q
    gemm_tf32<<<gg, 256, GEMM_SMEM_BYTES>>>(Xq, Wq, bq, (float*)gq, 1, 0.125f);
    gemm_tf32<<<gg, 256, GEMM_SMEM_BYTES>>>(Xk, Wk, bk, (float*)gk, 1, 1.0f);
    gemm_tf32<<<gg, 256, GEMM_SMEM_BYTES>>>(Xv, Wv, bv, (float*)gv, 1, 1.0f);

    attn_kernel<<<dim3(SEQ/128, BATCH*NHEAD), 256, ATTN_SMEM_BYTES>>>();

    gemm_tf32<<<gg, 256, GEMM_SMEM_BYTES>>>((const float*)gctx, Wo, bo, out, 0, 1.0f);
}

// round 2
// speedup vs baseline: 1.2864x; 1.2864x over previous
#include <cuda_runtime.h>
#include <cstdint>

#define SEQ    2048
#define BATCH  4
#define NHEAD  16
#define DK     64
#define DMODEL 1024
#define MROWS  (BATCH*SEQ)

// Scratch (allocation-free rule: device globals).
__device__ float g_q[BATCH*NHEAD*SEQ*DK];
__device__ float g_k[BATCH*NHEAD*SEQ*DK];
__device__ float g_v[BATCH*NHEAD*SEQ*DK];
__device__ float g_ctx[(size_t)MROWS*DMODEL];
// tf32-pre-rounded copies of raw inputs
__device__ float g_xq[(size_t)MROWS*DMODEL];
__device__ float g_xk[(size_t)MROWS*DMODEL];
__device__ float g_xv[(size_t)MROWS*DMODEL];
__device__ float g_wq[DMODEL*DMODEL];
__device__ float g_wk[DMODEL*DMODEL];
__device__ float g_wv[DMODEL*DMODEL];
__device__ float g_wo[DMODEL*DMODEL];

// ---------------- helpers ----------------
__device__ __forceinline__ uint32_t f2tf(float x){
    uint32_t r; asm("cvt.rna.tf32.f32 %0, %1;" : "=r"(r) : "f"(x)); return r;
}
__device__ __forceinline__ float tff(float x){ return __uint_as_float(f2tf(x)); }
__device__ __forceinline__ uint32_t saddr(const void* p){
    return (uint32_t)__cvta_generic_to_shared(p);
}
__device__ __forceinline__ void cp16(uint32_t s, const void* g){
    asm volatile("cp.async.cg.shared.global [%0], [%1], 16;\n" :: "r"(s), "l"(g));
}
__device__ __forceinline__ void cpcommit(){ asm volatile("cp.async.commit_group;\n"); }
template<int N> __device__ __forceinline__ void cpwait(){
    asm volatile("cp.async.wait_group %0;\n" :: "n"(N));
}
__device__ __forceinline__ void mma8(float c[4],
        uint32_t a0,uint32_t a1,uint32_t a2,uint32_t a3,
        uint32_t b0,uint32_t b1){
    asm volatile(
      "mma.sync.aligned.m16n8k8.row.col.f32.tf32.tf32.f32 "
      "{%0,%1,%2,%3},{%4,%5,%6,%7},{%8,%9},{%0,%1,%2,%3};\n"
      : "+f"(c[0]), "+f"(c[1]), "+f"(c[2]), "+f"(c[3])
      : "r"(a0), "r"(a1), "r"(a2), "r"(a3), "r"(b0), "r"(b1));
}

// ---------------- pre-round kernels (tf32 RNA) ----------------
__global__ void round3_kernel(const float4* __restrict__ a, const float4* __restrict__ b,
                              const float4* __restrict__ c, float4* __restrict__ oa,
                              float4* __restrict__ ob, float4* __restrict__ oc, int n4)
{
    int i = blockIdx.x*blockDim.x + threadIdx.x;
    if (i >= n4) return;
    const float4* s = (blockIdx.y==0) ? a : (blockIdx.y==1) ? b : c;
    float4* d       = (blockIdx.y==0) ? oa : (blockIdx.y==1) ? ob : oc;
    float4 v = s[i];
    v.x = tff(v.x); v.y = tff(v.y); v.z = tff(v.z); v.w = tff(v.w);
    d[i] = v;
}
__global__ void round4_kernel(const float4* __restrict__ a, const float4* __restrict__ b,
                              const float4* __restrict__ c, const float4* __restrict__ e,
                              float4* __restrict__ oa, float4* __restrict__ ob,
                              float4* __restrict__ oc, float4* __restrict__ oe, int n4)
{
    int i = blockIdx.x*blockDim.x + threadIdx.x;
    if (i >= n4) return;
    const float4* s = (blockIdx.y==0) ? a : (blockIdx.y==1) ? b : (blockIdx.y==2) ? c : e;
    float4* d       = (blockIdx.y==0) ? oa : (blockIdx.y==1) ? ob : (blockIdx.y==2) ? oc : oe;
    float4 v = s[i];
    v.x = tff(v.x); v.y = tff(v.y); v.z = tff(v.z); v.w = tff(v.w);
    d[i] = v;
}

// ---------------- GEMM: C[M,N] = X[M,K] @ W[N,K]^T + bias ----------------
// All operands pre-rounded to tf32 -> no cvt in inner loop.
// Block tile 256x128x32, 256 threads (8 warps as 4m x 2n), warp tile 64x64
// (mt=4 m16-tiles, nt=8 n8-tiles). Double-buffered cp.async.
// mode 0: dst[m*1024+n] = val (fp32)           (output projection)
// mode 1: head-split store to [B,H,S,64], scaled, tf32-rounded (QKV)
#define GEMM_SMEM_BYTES ((2*256*36 + 2*128*36)*4)

__global__ void __launch_bounds__(256,1) gemm_tf32(
    const float* __restrict__ A, const float* __restrict__ W,
    const float* __restrict__ bias, float* __restrict__ dst,
    int mode, float scale)
{
    extern __shared__ float sm[];
    float* sA = sm;                 // [2][256][36]
    float* sB = sm + 2*256*36;      // [2][128][36]
    const int tid = threadIdx.x;
    const int m0 = blockIdx.y << 8, n0 = blockIdx.x << 7;

    auto load_tile = [&](int buf, int kt){
        const float* Ag = A + (size_t)m0*DMODEL + kt*32;
        const float* Wg = W + (size_t)n0*DMODEL + kt*32;
        float* a = sA + buf*(256*36);
        float* b = sB + buf*(128*36);
#pragma unroll
        for (int i = 0; i < 8; ++i){
            int v = i*256 + tid;
            int r = v >> 3, c = (v & 7) << 2;
            cp16(saddr(a + r*36 + c), Ag + (size_t)r*DMODEL + c);
        }
#pragma unroll
        for (int i = 0; i < 4; ++i){
            int v = i*256 + tid;
            int r = v >> 3, c = (v & 7) << 2;
            cp16(saddr(b + r*36 + c), Wg + (size_t)r*DMODEL + c);
        }
        cpcommit();
    };

    float acc[4][8][4];
#pragma unroll
    for (int i=0;i<4;i++)
#pragma unroll
        for (int j=0;j<8;j++)
#pragma unroll
            for (int e=0;e<4;e++) acc[i][j][e] = 0.f;

    load_tile(0, 0);

    const int warp = tid >> 5, lane = tid & 31;
    const int wm = warp >> 1, wn = warp & 1;
    const int g = lane >> 2, tig = lane & 3;

    for (int kt = 0; kt < 32; ++kt){
        if (kt < 31){ load_tile((kt+1)&1, kt+1); cpwait<1>(); }
        else        { cpwait<0>(); }
        __syncthreads();
        const float* a = sA + (kt&1)*(256*36);
        const float* b = sB + (kt&1)*(128*36);
#pragma unroll
        for (int ks = 0; ks < 4; ++ks){
            uint32_t af[4][4];
#pragma unroll
            for (int mt = 0; mt < 4; ++mt){
                int r = wm*64 + mt*16 + g;
                int c = ks*8 + tig;
                af[mt][0] = __float_as_uint(a[r*36 + c]);
                af[mt][1] = __float_as_uint(a[(r+8)*36 + c]);
                af[mt][2] = __float_as_uint(a[r*36 + c + 4]);
                af[mt][3] = __float_as_uint(a[(r+8)*36 + c + 4]);
            }
#pragma unroll
            for (int nt = 0; nt < 8; ++nt){
                int n = wn*64 + nt*8 + g;
                int c = ks*8 + tig;
                uint32_t b0 = __float_as_uint(b[n*36 + c]);
                uint32_t b1 = __float_as_uint(b[n*36 + c + 4]);
#pragma unroll
                for (int mt = 0; mt < 4; ++mt)
                    mma8(acc[mt][nt], af[mt][0],af[mt][1],af[mt][2],af[mt][3], b0,b1);
            }
        }
        __syncthreads();
    }

    // epilogue (float2 stores: e-pairs are adjacent columns)
#pragma unroll
    for (int mt = 0; mt < 4; ++mt){
#pragma unroll
        for (int nt = 0; nt < 8; ++nt){
            int row = m0 + wm*64 + mt*16 + g;
            int col = n0 + wn*64 + nt*8 + 2*tig;
#pragma unroll
            for (int half = 0; half < 2; ++half){
                int r = row + half*8;
                float v0 = (acc[mt][nt][2*half+0] + bias[col])   * scale;
                float v1 = (acc[mt][nt][2*half+1] + bias[col+1]) * scale;
                if (mode == 0){
                    *(float2*)(dst + (size_t)r*DMODEL + col) = make_float2(v0, v1);
                } else {
                    int bb = r >> 11, s = r & 2047, h = col >> 6, d = col & 63;
                    *(float2*)(dst + (((size_t)(bb*NHEAD + h))*SEQ + s)*DK + d) =
                        make_float2(tff(v0), tff(v1));
                }
            }
        }
    }
}

// ---------------- Flash attention ----------------
// per (b,h), 128-row Q tiles, 8 warps x 16 rows (softmax warp-private).
// Double-buffered K/V chunks of 128 keys; online softmax in log2 domain
// (log2e folded into Q scale -> single-MUFU exp2f).
#define ATTN_SMEM_BYTES ((2*128*68 + 2*128*72 + 8*16*132)*4)

__global__ void __launch_bounds__(256,1) attn_kernel()
{
    extern __shared__ float sm[];
    float* sK = sm;                             // [2][128][68]
    float* sV = sm + 2*128*68;                  // [2][128][72] (stride 72: PV B-loads conflict-free)
    float* sP = sm + 2*128*68 + 2*128*72;       // [8][16][132]; also Q staging [128][68]

    const int tid  = threadIdx.x;
    const int warp = tid >> 5, lane = tid & 31;
    const int g = lane >> 2, tig = lane & 3;
    const int qt = blockIdx.x, bh = blockIdx.y;

    const float* qg  = g_q + ((size_t)bh*SEQ + qt*128)*DK;  // pre-scaled by log2e/8
    const float* kg0 = g_k + (size_t)bh*SEQ*DK;
    const float* vg0 = g_v + (size_t)bh*SEQ*DK;

    auto load_kv = [&](int buf, int kt){
        const float* kg = kg0 + (size_t)kt*128*DK;
        const float* vg = vg0 + (size_t)kt*128*DK;
        float* kb = sK + buf*(128*68);
        float* vb = sV + buf*(128*72);
#pragma unroll
        for (int i = 0; i < 8; ++i){
            int v = i*256 + tid;
            int r = v >> 4, c = (v & 15) << 2;
            cp16(saddr(kb + r*68 + c), kg + (size_t)r*DK + c);
            cp16(saddr(vb + r*72 + c), vg + (size_t)r*DK + c);
        }
        cpcommit();
    };

    // prologue: stage Q (into sP region) as its own group, then KV chunk 0
#pragma unroll
    for (int i = 0; i < 8; ++i){
        int v = i*256 + tid;
        int r = v >> 4, c = (v & 15) << 2;
        cp16(saddr(sP + r*68 + c), qg + (size_t)r*DK + c);
    }
    cpcommit();
    load_kv(0, 0);
    cpwait<1>();            // Q group done (KV0 may still be in flight)
    __syncthreads();

    uint32_t qa[8][4];
#pragma unroll
    for (int kk = 0; kk < 8; ++kk){
        int r = warp*16 + g;
        int c = kk*8 + tig;
        qa[kk][0] = __float_as_uint(sP[r*68 + c]);
        qa[kk][1] = __float_as_uint(sP[(r+8)*68 + c]);
        qa[kk][2] = __float_as_uint(sP[r*68 + c + 4]);
        qa[kk][3] = __float_as_uint(sP[(r+8)*68 + c + 4]);
    }

    float o[8][4];
#pragma unroll
    for (int j=0;j<8;j++)
#pragma unroll
        for (int e=0;e<4;e++) o[j][e] = 0.f;
    float rm0 = -1e30f, rm1 = -1e30f, rl0 = 0.f, rl1 = 0.f;

    float* myP = sP + warp*(16*132);

    for (int kt = 0; kt < 16; ++kt){
        __syncthreads();    // all warps done with prior compute (frees other buf; protects Q staging on kt=0)
        if (kt < 15){ load_kv((kt+1)&1, kt+1); cpwait<1>(); }
        else        { cpwait<0>(); }
        __syncthreads();    // current buf visible to all warps
        const float* kb = sK + (kt&1)*(128*68);
        const float* vb = sV + (kt&1)*(128*72);

        // S[16 x 128] = q @ K^T (q pre-scaled by log2e/sqrt(dk))
        float s[16][4];
#pragma unroll
        for (int j=0;j<16;j++)
#pragma unroll
            for (int e=0;e<4;e++) s[j][e] = 0.f;
#pragma unroll
        for (int kk = 0; kk < 8; ++kk){
#pragma unroll
            for (int nt = 0; nt < 16; ++nt){
                int n = nt*8 + g;
                int c = kk*8 + tig;
                uint32_t b0 = __float_as_uint(kb[n*68 + c]);
                uint32_t b1 = __float_as_uint(kb[n*68 + c + 4]);
                mma8(s[nt], qa[kk][0],qa[kk][1],qa[kk][2],qa[kk][3], b0,b1);
            }
        }

        // online softmax in log2 domain (rows g, g+8 private to this warp)
        float m0c = -1e30f, m1c = -1e30f;
#pragma unroll
        for (int nt = 0; nt < 16; ++nt){
            m0c = fmaxf(m0c, fmaxf(s[nt][0], s[nt][1]));
            m1c = fmaxf(m1c, fmaxf(s[nt][2], s[nt][3]));
        }
        m0c = fmaxf(m0c, __shfl_xor_sync(0xffffffffu, m0c, 1));
        m0c = fmaxf(m0c, __shfl_xor_sync(0xffffffffu, m0c, 2));
        m1c = fmaxf(m1c, __shfl_xor_sync(0xffffffffu, m1c, 1));
        m1c = fmaxf(m1c, __shfl_xor_sync(0xffffffffu, m1c, 2));
        float nm0 = fmaxf(rm0, m0c), nm1 = fmaxf(rm1, m1c);
        float cor0 = exp2f(rm0 - nm0), cor1 = exp2f(rm1 - nm1);
        rm0 = nm0; rm1 = nm1;

        float l0 = 0.f, l1 = 0.f;
#pragma unroll
        for (int nt = 0; nt < 16; ++nt){
            float p0 = exp2f(s[nt][0] - nm0);
            float p1 = exp2f(s[nt][1] - nm0);
            float p2 = exp2f(s[nt][2] - nm1);
            float p3 = exp2f(s[nt][3] - nm1);
            l0 += p0 + p1; l1 += p2 + p3;
            *(float2*)(myP + g*132     + nt*8 + 2*tig) = make_float2(tff(p0), tff(p1));
            *(float2*)(myP + (g+8)*132 + nt*8 + 2*tig) = make_float2(tff(p2), tff(p3));
        }
        l0 += __shfl_xor_sync(0xffffffffu, l0, 1);
        l0 += __shfl_xor_sync(0xffffffffu, l0, 2);
        l1 += __shfl_xor_sync(0xffffffffu, l1, 1);
        l1 += __shfl_xor_sync(0xffffffffu, l1, 2);
        rl0 = rl0*cor0 + l0;
        rl1 = rl1*cor1 + l1;

#pragma unroll
        for (int j = 0; j < 8; ++j){
            o[j][0]*=cor0; o[j][1]*=cor0; o[j][2]*=cor1; o[j][3]*=cor1;
        }
        __syncwarp();  // P writes visible to warp

        // O += P @ V
#pragma unroll
        for (int kk = 0; kk < 16; ++kk){
            int c = kk*8 + tig;
            uint32_t a0 = __float_as_uint(myP[g*132 + c]);
            uint32_t a1 = __float_as_uint(myP[(g+8)*132 + c]);
            uint32_t a2 = __float_as_uint(myP[g*132 + c + 4]);
            uint32_t a3 = __float_as_uint(myP[(g+8)*132 + c + 4]);
#pragma unroll
            for (int nt = 0; nt < 8; ++nt){
                uint32_t b0 = __float_as_uint(vb[c*72 + nt*8 + g]);
                uint32_t b1 = __float_as_uint(vb[(c+4)*72 + nt*8 + g]);
                mma8(o[nt], a0,a1,a2,a3, b0,b1);
            }
        }
        __syncwarp();  // done reading P before next chunk overwrites it
    }

    // normalize + write context [B,S,D], tf32-rounded (feeds final GEMM cvt-free)
    float il0 = 1.f/rl0, il1 = 1.f/rl1;
    int b = bh >> 4, h = bh & 15;
    int r0 = b*SEQ + qt*128 + warp*16 + g;
#pragma unroll
    for (int nt = 0; nt < 8; ++nt){
        int col = h*64 + nt*8 + 2*tig;
        *(float2*)(g_ctx + (size_t)r0*DMODEL + col) =
            make_float2(tff(o[nt][0]*il0), tff(o[nt][1]*il0));
        *(float2*)(g_ctx + (size_t)(r0+8)*DMODEL + col) =
            make_float2(tff(o[nt][2]*il1), tff(o[nt][3]*il1));
    }
}

// ---------------- launch ----------------
extern "C" void kernel_launch(void* const* d_in, const int* in_sizes, int n_in,
                              void* d_out, int out_size)
{
    const float* Xq = (const float*)d_in[0];
    const float* Xk = (const float*)d_in[1];
    const float* Xv = (const float*)d_in[2];
    const float* Wq = (const float*)d_in[3]; const float* bq = (const float*)d_in[4];
    const float* Wk = (const float*)d_in[5]; const float* bk = (const float*)d_in[6];
    const float* Wv = (const float*)d_in[7]; const float* bv = (const float*)d_in[8];
    const float* Wo = (const float*)d_in[9]; const float* bo = (const float*)d_in[10];
    float* out = (float*)d_out;

    void *gq, *gk, *gv, *gctx, *gxq, *gxk, *gxv, *gwq, *gwk, *gwv, *gwo;
    cudaGetSymbolAddress(&gq,  g_q);
    cudaGetSymbolAddress(&gk,  g_k);
    cudaGetSymbolAddress(&gv,  g_v);
    cudaGetSymbolAddress(&gctx, g_ctx);
    cudaGetSymbolAddress(&gxq, g_xq);
    cudaGetSymbolAddress(&gxk, g_xk);
    cudaGetSymbolAddress(&gxv, g_xv);
    cudaGetSymbolAddress(&gwq, g_wq);
    cudaGetSymbolAddress(&gwk, g_wk);
    cudaGetSymbolAddress(&gwv, g_wv);
    cudaGetSymbolAddress(&gwo, g_wo);

    cudaFuncSetAttribute(gemm_tf32,  cudaFuncAttributeMaxDynamicSharedMemorySize, GEMM_SMEM_BYTES);
    cudaFuncSetAttribute(attn_kernel, cudaFuncAttributeMaxDynamicSharedMemorySize, ATTN_SMEM_BYTES);

    // pre-round raw inputs to tf32 (RNA) once -> all GEMM inner loops cvt-free
    {
        int n4x = (MROWS*DMODEL)/4;      // 2,097,152
        dim3 gx((n4x + 255)/256, 3);
        round3_kernel<<<gx, 256>>>((const float4*)Xq, (const float4*)Xk, (const float4*)Xv,
                                   (float4*)gxq, (float4*)gxk, (float4*)gxv, n4x);
        int n4w = (DMODEL*DMODEL)/4;     // 262,144
        dim3 gw((n4w + 255)/256, 4);
        round4_kernel<<<gw, 256>>>((const float4*)Wq, (const float4*)Wk,
                                   (const float4*)Wv, (const float4*)Wo,
                                   (float4*)gwq, (float4*)gwk, (float4*)gwv, (float4*)gwo, n4w);
    }

    dim3 gg(DMODEL/128, MROWS/256);   // (8, 32)
    // Q projection: fold 1/sqrt(d_k) * log2(e) into Q (softmax runs in log2 domain)
    const float qscale = 0.125f * 1.4426950408889634f;
    gemm_tf32<<<gg, 256, GEMM_SMEM_BYTES>>>((const float*)gxq, (const float*)gwq, bq, (float*)gq, 1, qscale);
    gemm_tf32<<<gg, 256, GEMM_SMEM_BYTES>>>((const float*)gxk, (const float*)gwk, bk, (float*)gk, 1, 1.0f);
    gemm_tf32<<<gg, 256, GEMM_SMEM_BYTES>>>((const float*)gxv, (const float*)gwv, bv, (float*)gv, 1, 1.0f);

    attn_kernel<<<dim3(SEQ/128, BATCH*NHEAD), 256, ATTN_SMEM_BYTES>>>();

    gemm_tf32<<<gg, 256, GEMM_SMEM_BYTES>>>((const float*)gctx, (const float*)gwo, bo, out, 0, 1.0f);
}